// round 1
// baseline (speedup 1.0000x reference)
#include <cuda_runtime.h>
#include <cstdint>

#define S_LEN  2048
#define TB     16
#define NHEAD  4
#define NPOS   12
#define VBITS  10
#define OBITS  12

// Inputs (metadata order):
//  0: tokens       (S, 16)        int32  (0/1 bits)
//  1: route_table  (H, 1<<24)     int32  (0/1)
//  2: value_table  (H, 16, 1024)  float32
//  3: output_table (16, 4096)     float32
//  4: conns_value  (H, 16, 10)    int32  in [0, 28)
//  5: conns_out    (16, 12)       int32  in [0, 64)
// Output: (S, 16) float32

__global__ __launch_bounds__(128)
void poa_kernel(const int*   __restrict__ tokens,
                const int*   __restrict__ route_table,
                const float* __restrict__ value_table,
                const float* __restrict__ output_table,
                const int*   __restrict__ conns_value,
                const int*   __restrict__ conns_out,
                float*       __restrict__ out)
{
    __shared__ int      s_cv[NHEAD * TB * VBITS];  // 640 ints
    __shared__ int      s_co[TB * OBITS];          // 192 ints
    __shared__ unsigned s_chead[NHEAD];

    const int tid  = threadIdx.x;
    const int i    = blockIdx.x;          // position
    const int h    = tid >> 5;            // head = warp id
    const int lane = tid & 31;

    // Preload the tiny connection tables into shared.
    for (int k = tid; k < NHEAD * TB * VBITS; k += 128) s_cv[k] = conns_value[k];
    for (int k = tid; k < TB * OBITS;        k += 128) s_co[k] = conns_out[k];

    // ---- 1) warp h: find first j with route_table[h, i<<12 | j] > 0 ----
    const long long base = ((long long)h << 24) | ((long long)i << NPOS);
    int j = -1;
    for (int j0 = 0; j0 < S_LEN; j0 += 32) {
        int v = route_table[base + j0 + lane];
        unsigned m = __ballot_sync(0xffffffffu, v > 0);
        if (m) { j = j0 + __ffs(m) - 1; break; }
    }
    const bool has_any = (j >= 0);
    const int  jj = has_any ? j : 0;

    // ---- 2) build vinmask[jj]: bits 0..15 = tokens[jj], bits 16..27 = pos bits (MSB-first) ----
    bool p;
    if      (lane < 16) p = tokens[jj * TB + lane] > 0;
    else if (lane < 28) p = ((jj >> (27 - lane)) & 1) != 0;   // vin[16+m] = (j >> (11-m)) & 1
    else                p = false;
    const unsigned vinmask = __ballot_sync(0xffffffffu, p);

    __syncthreads();  // shared conns ready

    // ---- 3) lane t<16: value lookup -> combined bit ----
    bool cbit = false;
    if (lane < TB && has_any) {
        const int* cv = &s_cv[(h * TB + lane) * VBITS];
        int vaddr = 0;
        #pragma unroll
        for (int b = 0; b < VBITS; b++)
            vaddr = (vaddr << 1) | (int)((vinmask >> cv[b]) & 1u);
        float val = value_table[(h * TB + lane) * (1 << VBITS) + vaddr];
        cbit = val > 0.5f;
    }
    const unsigned mask16 = __ballot_sync(0xffffffffu, cbit) & 0xffffu;
    if (lane == 0) s_chead[h] = mask16;
    __syncthreads();

    // ---- 4) warp 0, lanes t<16: output lookup ----
    if (tid < TB) {
        unsigned long long comb =
              (unsigned long long)s_chead[0]
            | ((unsigned long long)s_chead[1] << 16)
            | ((unsigned long long)s_chead[2] << 32)
            | ((unsigned long long)s_chead[3] << 48);
        const int* co = &s_co[tid * OBITS];
        int oaddr = 0;
        #pragma unroll
        for (int b = 0; b < OBITS; b++)
            oaddr = (oaddr << 1) | (int)((comb >> co[b]) & 1ull);
        out[i * TB + tid] = output_table[tid * (1 << OBITS) + oaddr];
    }
}

extern "C" void kernel_launch(void* const* d_in, const int* in_sizes, int n_in,
                              void* d_out, int out_size)
{
    const int*   tokens       = (const int*)  d_in[0];
    const int*   route_table  = (const int*)  d_in[1];
    const float* value_table  = (const float*)d_in[2];
    const float* output_table = (const float*)d_in[3];
    const int*   conns_value  = (const int*)  d_in[4];
    const int*   conns_out    = (const int*)  d_in[5];
    float*       out          = (float*)      d_out;

    poa_kernel<<<S_LEN, 128>>>(tokens, route_table, value_table, output_table,
                               conns_value, conns_out, out);
}

// round 2
// speedup vs baseline: 1.3077x; 1.3077x over previous
#include <cuda_runtime.h>
#include <cstdint>

#define S_LEN  2048
#define TB     16
#define NHEAD  4
#define NPOS   12
#define VBITS  10
#define OBITS  12
#define WARPS_PER_BLK 8   // one warp per position

// Inputs (metadata order):
//  0: tokens       (S, 16)        int32  (0/1 bits)
//  1: route_table  (H, 1<<24)     int32  (0/1)
//  2: value_table  (H, 16, 1024)  float32
//  3: output_table (16, 4096)     float32
//  4: conns_value  (H, 16, 10)    int32  in [0, 28)
//  5: conns_out    (16, 12)       int32  in [0, 64)
// Output: (S, 16) float32

__global__ __launch_bounds__(WARPS_PER_BLK * 32)
void poa_kernel(const int*   __restrict__ tokens,
                const int*   __restrict__ route_table,
                const float* __restrict__ value_table,
                const float* __restrict__ output_table,
                const int*   __restrict__ conns_value,
                const int*   __restrict__ conns_out,
                float*       __restrict__ out)
{
    __shared__ int s_cv[NHEAD * TB * VBITS];  // 640 ints
    __shared__ int s_co[TB * OBITS];          // 192 ints

    const int tid  = threadIdx.x;
    const int lane = tid & 31;
    const int wid  = tid >> 5;
    const int i    = blockIdx.x * WARPS_PER_BLK + wid;   // position

    // Preload tiny connection tables (shared across the 8 warps of this block).
    for (int k = tid; k < NHEAD * TB * VBITS; k += WARPS_PER_BLK * 32) s_cv[k] = conns_value[k];
    for (int k = tid; k < TB * OBITS;        k += WARPS_PER_BLK * 32) s_co[k] = conns_out[k];

    // ---- 1) route scan: lanes (h = lane>>3, j = lane&7) probe first 8 j's per head ----
    {
        const int h0 = lane >> 3;
        const int jl = lane & 7;
        int v = route_table[(h0 << 24) | (i << NPOS) | jl];
        unsigned m = __ballot_sync(0xffffffffu, v > 0);

        int  j0v = 0, j1v = 0, j2v = 0, j3v = 0;
        bool a0 = false, a1 = false, a2 = false, a3 = false;

        #define FIND_J(H, JV, AV)                                                      \
        {                                                                              \
            unsigned mh = (m >> (8 * (H))) & 0xffu;                                    \
            if (mh) { JV = __ffs(mh) - 1; AV = true; }                                 \
            else {                                                                     \
                const int base = ((H) << 24) | (i << NPOS);                            \
                for (int js = 8; js < S_LEN; js += 32) {                               \
                    int vv = route_table[base + js + lane];                            \
                    unsigned mm = __ballot_sync(0xffffffffu, vv > 0);                  \
                    if (mm) { JV = js + __ffs(mm) - 1; AV = true; break; }             \
                }                                                                      \
            }                                                                          \
        }
        FIND_J(0, j0v, a0)
        FIND_J(1, j1v, a1)
        FIND_J(2, j2v, a2)
        FIND_J(3, j3v, a3)
        #undef FIND_J

        // ---- 2) token masks for all 4 heads via two ballots ----
        // ballot_lo: lane -> (hA = lane>>4 in {0,1}, b = lane&15)
        // ballot_hi: lane -> (hB = hA+2,             b = lane&15)
        const bool hiA = (lane & 16) != 0;
        const int  b   = lane & 15;
        const int  jA  = hiA ? j1v : j0v;
        const int  jB  = hiA ? j3v : j2v;

        int tA = tokens[jA * TB + b];
        int tB = tokens[jB * TB + b];
        unsigned blo = __ballot_sync(0xffffffffu, tA > 0);
        unsigned bhi = __ballot_sync(0xffffffffu, tB > 0);

        // vin mask per head: bits 0..15 tokens, bits 16..27 pos bits (MSB-first pack)
        // bit(16+m) = (j >> (11-m)) & 1  ==  (__brev(j) >> 4) bit (16+m)
        unsigned v0 = (blo & 0xffffu) | ((__brev((unsigned)j0v) >> 4) & 0x0fff0000u);
        unsigned v1 = (blo >> 16)     | ((__brev((unsigned)j1v) >> 4) & 0x0fff0000u);
        unsigned v2 = (bhi & 0xffffu) | ((__brev((unsigned)j2v) >> 4) & 0x0fff0000u);
        unsigned v3 = (bhi >> 16)     | ((__brev((unsigned)j3v) >> 4) & 0x0fff0000u);

        const unsigned vA = hiA ? v1 : v0;
        const unsigned vB = hiA ? v3 : v2;
        const bool     aA = hiA ? a1 : a0;
        const bool     aB = hiA ? a3 : a2;
        const int      hA = hiA ? 1 : 0;
        const int      hB = hA + 2;

        __syncthreads();  // conns tables ready

        // ---- 3) value lookups: this lane covers (hA,b) and (hB,b) ----
        bool c1 = false, c2 = false;
        {
            const int* cv = &s_cv[(hA * TB + b) * VBITS];
            int va = 0;
            #pragma unroll
            for (int k = 0; k < VBITS; k++) va = (va << 1) | (int)((vA >> cv[k]) & 1u);
            float val = value_table[(hA * TB + b) * (1 << VBITS) + va];
            c1 = aA && (val > 0.5f);
        }
        {
            const int* cv = &s_cv[(hB * TB + b) * VBITS];
            int va = 0;
            #pragma unroll
            for (int k = 0; k < VBITS; k++) va = (va << 1) | (int)((vB >> cv[k]) & 1u);
            float val = value_table[(hB * TB + b) * (1 << VBITS) + va];
            c2 = aB && (val > 0.5f);
        }
        unsigned clo = __ballot_sync(0xffffffffu, c1);  // head0 bits 0-15, head1 16-31
        unsigned chi = __ballot_sync(0xffffffffu, c2);  // head2 bits 0-15, head3 16-31
        unsigned long long comb = (unsigned long long)clo
                                | ((unsigned long long)chi << 32);

        // ---- 4) output lookup: lanes 0-15 ----
        if (lane < TB) {
            const int* co = &s_co[lane * OBITS];
            int oa = 0;
            #pragma unroll
            for (int k = 0; k < OBITS; k++) oa = (oa << 1) | (int)((comb >> co[k]) & 1ull);
            out[i * TB + lane] = output_table[lane * (1 << OBITS) + oa];
        }
    }
}

extern "C" void kernel_launch(void* const* d_in, const int* in_sizes, int n_in,
                              void* d_out, int out_size)
{
    const int*   tokens       = (const int*)  d_in[0];
    const int*   route_table  = (const int*)  d_in[1];
    const float* value_table  = (const float*)d_in[2];
    const float* output_table = (const float*)d_in[3];
    const int*   conns_value  = (const int*)  d_in[4];
    const int*   conns_out    = (const int*)  d_in[5];
    float*       out          = (float*)      d_out;

    poa_kernel<<<S_LEN / WARPS_PER_BLK, WARPS_PER_BLK * 32>>>(
        tokens, route_table, value_table, output_table,
        conns_value, conns_out, out);
}

// round 3
// speedup vs baseline: 1.3140x; 1.0048x over previous
#include <cuda_runtime.h>
#include <cstdint>

#define S_LEN  2048
#define TB     16
#define NHEAD  4
#define NPOS   12
#define VBITS  10
#define OBITS  12
#define WARPS_PER_BLK 16   // one warp per position, 512 threads/block, 128 blocks

// Inputs (metadata order):
//  0: tokens       (S, 16)        int32  (0/1 bits)
//  1: route_table  (H, 1<<24)     int32  (0/1)
//  2: value_table  (H, 16, 1024)  float32
//  3: output_table (16, 4096)     float32
//  4: conns_value  (H, 16, 10)    int32  in [0, 28)
//  5: conns_out    (16, 12)       int32  in [0, 64)
// Output: (S, 16) float32

__global__ __launch_bounds__(WARPS_PER_BLK * 32)
void poa_kernel(const int*   __restrict__ tokens,
                const int*   __restrict__ route_table,
                const float* __restrict__ value_table,
                const float* __restrict__ output_table,
                const int*   __restrict__ conns_value,
                const int*   __restrict__ conns_out,
                float*       __restrict__ out)
{
    // Conn tables staged in shared; int4-aligned. cv=640 ints, co=192 ints.
    __shared__ __align__(16) int s_cv[NHEAD * TB * VBITS];
    __shared__ __align__(16) int s_co[TB * OBITS];

    const int tid  = threadIdx.x;
    const int lane = tid & 31;
    const int wid  = tid >> 5;
    const int i    = blockIdx.x * WARPS_PER_BLK + wid;   // position

    // Vectorized preload: 640/4=160 + 192/4=48 = 208 int4 over 512 threads.
    if (tid < NHEAD * TB * VBITS / 4)
        ((int4*)s_cv)[tid] = ((const int4*)conns_value)[tid];
    else if (tid < NHEAD * TB * VBITS / 4 + TB * OBITS / 4) {
        int k = tid - NHEAD * TB * VBITS / 4;
        ((int4*)s_co)[k] = ((const int4*)conns_out)[k];
    }

    // ---- 1) route scan: lanes (h = lane>>3, j = lane&7) probe first 8 j's/head ----
    const int h0 = lane >> 3;
    const int jl = lane & 7;
    int v = route_table[(h0 << 24) | (i << NPOS) | jl];
    unsigned m = __ballot_sync(0xffffffffu, v > 0);

    int  j0v = 0, j1v = 0, j2v = 0, j3v = 0;
    bool a0 = false, a1 = false, a2 = false, a3 = false;

    #define FIND_J(H, JV, AV)                                                      \
    {                                                                              \
        unsigned mh = (m >> (8 * (H))) & 0xffu;                                    \
        if (mh) { JV = __ffs(mh) - 1; AV = true; }                                 \
        else {                                                                     \
            const int base = ((H) << 24) | (i << NPOS);                            \
            for (int js = 8; js < S_LEN; js += 32) {                               \
                int vv = route_table[base + js + lane];                            \
                unsigned mm = __ballot_sync(0xffffffffu, vv > 0);                  \
                if (mm) { JV = js + __ffs(mm) - 1; AV = true; break; }             \
            }                                                                      \
        }                                                                          \
    }
    FIND_J(0, j0v, a0)
    FIND_J(1, j1v, a1)
    FIND_J(2, j2v, a2)
    FIND_J(3, j3v, a3)
    #undef FIND_J

    // ---- 2) token masks for all 4 heads via two ballots ----
    const bool hiA = (lane & 16) != 0;
    const int  b   = lane & 15;
    const int  jA  = hiA ? j1v : j0v;
    const int  jB  = hiA ? j3v : j2v;

    int tA = tokens[jA * TB + b];
    int tB = tokens[jB * TB + b];
    unsigned blo = __ballot_sync(0xffffffffu, tA > 0);
    unsigned bhi = __ballot_sync(0xffffffffu, tB > 0);

    // vin mask per head: bits 0..15 tokens, bits 16..27 pos bits (MSB-first pack)
    unsigned v0 = (blo & 0xffffu) | ((__brev((unsigned)j0v) >> 4) & 0x0fff0000u);
    unsigned v1 = (blo >> 16)     | ((__brev((unsigned)j1v) >> 4) & 0x0fff0000u);
    unsigned v2 = (bhi & 0xffffu) | ((__brev((unsigned)j2v) >> 4) & 0x0fff0000u);
    unsigned v3 = (bhi >> 16)     | ((__brev((unsigned)j3v) >> 4) & 0x0fff0000u);

    const unsigned vA = hiA ? v1 : v0;
    const unsigned vB = hiA ? v3 : v2;
    const bool     aA = hiA ? a1 : a0;
    const bool     aB = hiA ? a3 : a2;
    const int      hA = hiA ? 1 : 0;
    const int      hB = hA + 2;

    __syncthreads();  // conns tables ready

    // ---- 3) value lookups: this lane covers (hA,b) and (hB,b) ----
    bool c1 = false, c2 = false;
    {
        const int* cv = &s_cv[(hA * TB + b) * VBITS];
        int va = 0;
        #pragma unroll
        for (int k = 0; k < VBITS; k++) va = (va << 1) | (int)((vA >> cv[k]) & 1u);
        float val = value_table[(hA * TB + b) * (1 << VBITS) + va];
        c1 = aA && (val > 0.5f);
    }
    {
        const int* cv = &s_cv[(hB * TB + b) * VBITS];
        int va = 0;
        #pragma unroll
        for (int k = 0; k < VBITS; k++) va = (va << 1) | (int)((vB >> cv[k]) & 1u);
        float val = value_table[(hB * TB + b) * (1 << VBITS) + va];
        c2 = aB && (val > 0.5f);
    }
    unsigned clo = __ballot_sync(0xffffffffu, c1);  // head0 bits 0-15, head1 16-31
    unsigned chi = __ballot_sync(0xffffffffu, c2);  // head2 bits 0-15, head3 16-31
    unsigned long long comb = (unsigned long long)clo
                            | ((unsigned long long)chi << 32);

    // ---- 4) output lookup: lanes 0-15 ----
    if (lane < TB) {
        const int* co = &s_co[lane * OBITS];
        int oa = 0;
        #pragma unroll
        for (int k = 0; k < OBITS; k++) oa = (oa << 1) | (int)((comb >> co[k]) & 1ull);
        out[i * TB + lane] = output_table[lane * (1 << OBITS) + oa];
    }
}

extern "C" void kernel_launch(void* const* d_in, const int* in_sizes, int n_in,
                              void* d_out, int out_size)
{
    const int*   tokens       = (const int*)  d_in[0];
    const int*   route_table  = (const int*)  d_in[1];
    const float* value_table  = (const float*)d_in[2];
    const float* output_table = (const float*)d_in[3];
    const int*   conns_value  = (const int*)  d_in[4];
    const int*   conns_out    = (const int*)  d_in[5];
    float*       out          = (float*)      d_out;

    poa_kernel<<<S_LEN / WARPS_PER_BLK, WARPS_PER_BLK * 32>>>(
        tokens, route_table, value_table, output_table,
        conns_value, conns_out, out);
}